// round 14
// baseline (speedup 1.0000x reference)
#include <cuda_runtime.h>
#include <cuda_bf16.h>
#include <cstdint>
#include <cstddef>

#define BB 4
#define CC 512
#define NN_ 4096
#define C8 64

// ---------------- scratch (__device__ globals; allocation-free rule) -------
__device__ __align__(128) __nv_bfloat16 g_xth[(size_t)BB * NN_ * CC];  // x^T hi [b,n,c]
__device__ __align__(128) __nv_bfloat16 g_xtl[(size_t)BB * NN_ * CC];  // x^T lo
__device__ __align__(128) __nv_bfloat16 g_wqkh[2 * C8 * CC];           // [Wq;Wk] hi
__device__ __align__(128) __nv_bfloat16 g_wqkl[2 * C8 * CC];           // [Wq;Wk] lo
__device__ __align__(128) float g_bqk[2 * C8];                          // [bq;bk]
__device__ __align__(128) __nv_bfloat16 g_wvh[CC * CC];                // Wv hi
__device__ __align__(128) __nv_bfloat16 g_qkth[(size_t)BB * NN_ * 2 * C8]; // qk^T hi
__device__ __align__(128) __nv_bfloat16 g_qktl[(size_t)BB * NN_ * 2 * C8]; // qk^T lo
__device__ __align__(128) __nv_bfloat16 g_vh[(size_t)BB * CC * NN_];   // v hi [b,c,n]
__device__ __align__(128) __nv_bfloat16 g_sh[(size_t)BB * NN_ * NN_];  // e=exp(att)
__device__ __align__(128) float g_rowsum[(size_t)BB * NN_];            // sum_j e [b,i]

// ---------------- helpers ---------------------------------------------------
__device__ __forceinline__ uint32_t smem_u32(const void* p) {
    uint32_t a;
    asm("{ .reg .u64 t; cvta.to.shared.u64 t, %1; cvt.u32.u64 %0, t; }"
        : "=r"(a) : "l"(p));
    return a;
}
__device__ __forceinline__ void cp16(uint32_t dst, const void* src) {
    asm volatile("cp.async.cg.shared.global [%0], [%1], 16;" :: "r"(dst), "l"(src));
}
template <int N>
__device__ __forceinline__ void wait_group() {
    asm volatile("cp.async.wait_group %0;" :: "n"(N) : "memory");
}
__device__ __forceinline__ void ldsm4(uint32_t* r, uint32_t addr) {
    asm volatile("ldmatrix.sync.aligned.m8n8.x4.shared.b16 {%0,%1,%2,%3}, [%4];"
                 : "=r"(r[0]), "=r"(r[1]), "=r"(r[2]), "=r"(r[3]) : "r"(addr));
}
__device__ __forceinline__ void mma16816(float* d, const uint32_t* a, const uint32_t* b) {
    asm volatile(
        "mma.sync.aligned.m16n8k16.row.col.f32.bf16.bf16.f32 "
        "{%0,%1,%2,%3}, {%4,%5,%6,%7}, {%8,%9}, {%0,%1,%2,%3};"
        : "+f"(d[0]), "+f"(d[1]), "+f"(d[2]), "+f"(d[3])
        : "r"(a[0]), "r"(a[1]), "r"(a[2]), "r"(a[3]), "r"(b[0]), "r"(b[1]));
}
__device__ __forceinline__ void split_bf16(float v, __nv_bfloat16& h, __nv_bfloat16& l) {
    h = __float2bfloat16(v);
    l = __float2bfloat16(v - __bfloat162float(h));
}

// ---------------------------------------------------------------------------
// bf16 HMMA GEMM, multistage cp.async pipeline (single barrier / iteration).
//   C[b,m,n] = sum_k A(m,k)*B(n,k),  b = bbase + blockIdx.z
// TERMS: 3 = (Ah+Al)x(Bh+Bl); 2 = (Ah+Al)xBh; 1 = AhxBh.
// OUTMODE: 0 = fp32 (opt. gamma*acc*invrowsum + resid), 1 = split bf16 hi+lo,
//          2 = bf16 hi only, 3 = bf16 exp(acc) + row-sum atomics.
// RS: in mode 0, scale acc by 1/rowsum[b,n]. TRANS_OUT: output [n][m].
// XM: blockIdx.x = m. Block: 256 thr = 8 warps (2x4). BK = 32. STAGES >= 3.
// ---------------------------------------------------------------------------
template <int BM, int BN, int TERMS, int STAGES, bool TRANS_OUT, int OUTMODE,
          bool HAS_BIAS, bool HAS_RESID, bool XM, bool RS>
__global__ void __launch_bounds__(256)
mma_gemm(const __nv_bfloat16* __restrict__ Ah, const __nv_bfloat16* __restrict__ Al,
         const __nv_bfloat16* __restrict__ Bh, const __nv_bfloat16* __restrict__ Bl,
         int K, int lda, int ldb, size_t sA, size_t sB,
         const float* __restrict__ bias,
         float* __restrict__ Cf,
         __nv_bfloat16* __restrict__ Oh, __nv_bfloat16* __restrict__ Ol,
         int ldc, size_t sC,
         const float* __restrict__ resid, const float* __restrict__ gamma,
         float* __restrict__ rowsum, int bbase) {
    constexpr int AH = (TERMS >= 2) ? 2 : 1;   // A halves staged
    constexpr int BH = (TERMS >= 3) ? 2 : 1;   // B halves staged
    constexpr int LDSS = 40;                   // padded k-stride (bf16)
    constexpr int A_HALF = BM * LDSS;
    constexpr int B_HALF = BN * LDSS;
    constexpr int BOFF = STAGES * AH * A_HALF; // B area start (elems)
    extern __shared__ __nv_bfloat16 sm[];

    const int tid = threadIdx.x;
    const int lane = tid & 31, warp = tid >> 5;
    const int wm = warp >> 2, wn = warp & 3;
    constexpr int WTM = BM / 2, WTN = BN / 4;
    constexpr int MT = WTM / 16, NT = WTN / 8;

    const int bm0 = (XM ? blockIdx.x : blockIdx.y) * BM;
    const int bn0 = (XM ? blockIdx.y : blockIdx.x) * BN;
    const int b = bbase + blockIdx.z;
    const __nv_bfloat16* aptr[2] = {Ah + (size_t)b * sA,
                                    (AH > 1) ? Al + (size_t)b * sA : Ah};
    const __nv_bfloat16* bptr[2] = {Bh + (size_t)b * sB,
                                    (BH > 1) ? Bl + (size_t)b * sB : Bh};
    const uint32_t smb = smem_u32(sm);

    const int mat = lane >> 3, r8 = lane & 7;
    const uint32_t lmoff = 2 * (((mat & 1) * 8 + r8) * LDSS + (mat >> 1) * 8);

    float acc[MT][NT][4];
#pragma unroll
    for (int i = 0; i < MT; i++)
#pragma unroll
        for (int j = 0; j < NT; j++)
#pragma unroll
            for (int e = 0; e < 4; e++) acc[i][j][e] = 0.f;

    auto load_stage = [&](int stage, int kt) {
        constexpr int CA = BM * 4 * AH / 256;
#pragma unroll
        for (int i = 0; i < CA; i++) {
            int idx = tid + i * 256;
            int half = idx / (BM * 4);
            int rem = idx - half * BM * 4;
            int r = rem >> 2, seg = rem & 3;
            const __nv_bfloat16* src =
                aptr[half] + (size_t)(bm0 + r) * lda + kt * 32 + seg * 8;
            uint32_t dst = smb + ((stage * AH + half) * A_HALF + r * LDSS + seg * 8) * 2;
            cp16(dst, src);
        }
        constexpr int CB = BN * 4 * BH / 256;
#pragma unroll
        for (int i = 0; i < CB; i++) {
            int idx = tid + i * 256;
            int half = idx / (BN * 4);
            int rem = idx - half * BN * 4;
            int r = rem >> 2, seg = rem & 3;
            const __nv_bfloat16* src =
                bptr[half] + (size_t)(bn0 + r) * ldb + kt * 32 + seg * 8;
            uint32_t dst = smb +
                (BOFF + (stage * BH + half) * B_HALF + r * LDSS + seg * 8) * 2;
            cp16(dst, src);
        }
        asm volatile("cp.async.commit_group;" ::: "memory");
    };

    const int KT = K / 32;
#pragma unroll
    for (int i = 0; i < STAGES - 1; i++)
        if (i < KT) load_stage(i, i);

    for (int kt = 0; kt < KT; kt++) {
        const int rem = KT - 1 - kt;
        if (rem >= STAGES - 2) wait_group<STAGES - 2>();
        else if (STAGES >= 4 && rem == 2) wait_group<2>();
        else if (rem == 1) wait_group<1>();
        else wait_group<0>();
        __syncthreads();
        if (kt + STAGES - 1 < KT)
            load_stage((kt + STAGES - 1) % STAGES, kt + STAGES - 1);

        const int s = kt % STAGES;
        const uint32_t aHi = smb + 2 * ((s * AH) * A_HALF);
        const uint32_t bHi = smb + 2 * (BOFF + (s * BH) * B_HALF);
#pragma unroll
        for (int ks = 0; ks < 2; ks++) {
            const int kk = ks * 16;
            uint32_t bh[NT][2], bl[NT][2];
#pragma unroll
            for (int p = 0; p < NT / 2; p++) {
                uint32_t t[4];
                uint32_t ab = bHi + 2 * ((wn * WTN + p * 16) * LDSS + kk) + lmoff;
                ldsm4(t, ab);
                bh[2 * p][0] = t[0]; bh[2 * p + 1][0] = t[1];
                bh[2 * p][1] = t[2]; bh[2 * p + 1][1] = t[3];
                if constexpr (BH > 1) {
                    ldsm4(t, ab + 2 * B_HALF);
                    bl[2 * p][0] = t[0]; bl[2 * p + 1][0] = t[1];
                    bl[2 * p][1] = t[2]; bl[2 * p + 1][1] = t[3];
                }
            }
#pragma unroll
            for (int mt = 0; mt < MT; mt++) {
                uint32_t ah[4], al[4];
                uint32_t aa = aHi + 2 * ((wm * WTM + mt * 16) * LDSS + kk) + lmoff;
                ldsm4(ah, aa);
                if constexpr (AH > 1) ldsm4(al, aa + 2 * A_HALF);
#pragma unroll
                for (int nt = 0; nt < NT; nt++) {
                    mma16816(acc[mt][nt], ah, bh[nt]);
                    if constexpr (BH > 1) mma16816(acc[mt][nt], ah, bl[nt]);
                    if constexpr (AH > 1) mma16816(acc[mt][nt], al, bh[nt]);
                }
            }
        }
    }
    __syncthreads();

    float g = 1.f;
    if constexpr (HAS_RESID) g = __ldg(gamma);

#pragma unroll
    for (int mt = 0; mt < MT; mt++) {
        const int r = bm0 + wm * WTM + mt * 16 + (lane >> 2);
        float bi0 = 0.f, bi1 = 0.f;
        if constexpr (HAS_BIAS) { bi0 = bias[r]; bi1 = bias[r + 8]; }
        float sum_r = 0.f, sum_r8 = 0.f;
#pragma unroll
        for (int nt = 0; nt < NT; nt++) {
            const int c = bn0 + wn * WTN + nt * 8 + (lane & 3) * 2;
            float v[4] = {acc[mt][nt][0] + bi0, acc[mt][nt][1] + bi0,
                          acc[mt][nt][2] + bi1, acc[mt][nt][3] + bi1};
            if constexpr (OUTMODE == 3) {
                __nv_bfloat16 e[4];
#pragma unroll
                for (int q = 0; q < 4; q++) e[q] = __float2bfloat16(__expf(v[q]));
                sum_r  += __bfloat162float(e[0]) + __bfloat162float(e[1]);
                sum_r8 += __bfloat162float(e[2]) + __bfloat162float(e[3]);
                size_t i0 = (size_t)b * sC + (size_t)r * ldc + c;
                size_t i1 = (size_t)b * sC + (size_t)(r + 8) * ldc + c;
                *reinterpret_cast<__nv_bfloat162*>(&Oh[i0]) = __nv_bfloat162(e[0], e[1]);
                *reinterpret_cast<__nv_bfloat162*>(&Oh[i1]) = __nv_bfloat162(e[2], e[3]);
            } else if constexpr (!TRANS_OUT) {
#pragma unroll
                for (int p = 0; p < 2; p++) {
                    const int row = r + p * 8;
                    size_t idx = (size_t)b * sC + (size_t)row * ldc + c;
                    if constexpr (OUTMODE == 1) {
                        __nv_bfloat16 h0, l0, h1, l1;
                        split_bf16(v[p * 2 + 0], h0, l0);
                        split_bf16(v[p * 2 + 1], h1, l1);
                        *reinterpret_cast<__nv_bfloat162*>(&Oh[idx]) =
                            __nv_bfloat162(h0, h1);
                        *reinterpret_cast<__nv_bfloat162*>(&Ol[idx]) =
                            __nv_bfloat162(l0, l1);
                    } else if constexpr (OUTMODE == 2) {
                        *reinterpret_cast<__nv_bfloat162*>(&Oh[idx]) =
                            __nv_bfloat162(__float2bfloat16(v[p * 2 + 0]),
                                           __float2bfloat16(v[p * 2 + 1]));
                    } else {
                        float s0 = 1.f, s1 = 1.f;
                        if constexpr (RS) {
                            float2 rsv = *reinterpret_cast<const float2*>(
                                &rowsum[(size_t)b * NN_ + c]);
                            s0 = 1.0f / rsv.x;
                            s1 = 1.0f / rsv.y;
                        }
                        float2 o;
                        if constexpr (HAS_RESID) {
                            float2 rx = *reinterpret_cast<const float2*>(&resid[idx]);
                            o.x = g * v[p * 2 + 0] * s0 + rx.x;
                            o.y = g * v[p * 2 + 1] * s1 + rx.y;
                        } else {
                            o.x = v[p * 2 + 0] * s0;
                            o.y = v[p * 2 + 1] * s1;
                        }
                        *reinterpret_cast<float2*>(&Cf[idx]) = o;
                    }
                }
            } else {
                const int rr[4] = {r, r, r + 8, r + 8};
                const int ccx[4] = {c, c + 1, c, c + 1};
#pragma unroll
                for (int e = 0; e < 4; e++) {
                    size_t idx = (size_t)b * sC + (size_t)ccx[e] * ldc + rr[e];
                    if constexpr (OUTMODE == 1) {
                        __nv_bfloat16 h, l;
                        split_bf16(v[e], h, l);
                        Oh[idx] = h;
                        Ol[idx] = l;
                    } else if constexpr (OUTMODE == 2) {
                        Oh[idx] = __float2bfloat16(v[e]);
                    } else {
                        Cf[idx] = v[e];
                    }
                }
            }
        }
        if constexpr (OUTMODE == 3) {
            sum_r  += __shfl_xor_sync(0xffffffffu, sum_r, 1);
            sum_r  += __shfl_xor_sync(0xffffffffu, sum_r, 2);
            sum_r8 += __shfl_xor_sync(0xffffffffu, sum_r8, 1);
            sum_r8 += __shfl_xor_sync(0xffffffffu, sum_r8, 2);
            if ((lane & 3) == 0) {
                atomicAdd(&rowsum[(size_t)b * NN_ + r], sum_r);
                atomicAdd(&rowsum[(size_t)b * NN_ + r + 8], sum_r8);
            }
        }
    }
}

// ---------------------------------------------------------------------------
__global__ void __launch_bounds__(256)
transpose_split_x(const float* __restrict__ x,
                  __nv_bfloat16* __restrict__ th, __nv_bfloat16* __restrict__ tl) {
    __shared__ float t[32][33];
    const int b = blockIdx.z;
    const int c0 = blockIdx.y * 32, n0 = blockIdx.x * 32;
    const float* xp = x + (size_t)b * CC * NN_;
#pragma unroll
    for (int i = threadIdx.y; i < 32; i += 8)
        t[i][threadIdx.x] = xp[(size_t)(c0 + i) * NN_ + n0 + threadIdx.x];
    __syncthreads();
    __nv_bfloat16* hp = th + (size_t)b * NN_ * CC;
    __nv_bfloat16* lp = tl + (size_t)b * NN_ * CC;
#pragma unroll
    for (int i = threadIdx.y; i < 32; i += 8) {
        float v = t[threadIdx.x][i];
        __nv_bfloat16 h, l;
        split_bf16(v, h, l);
        size_t idx = (size_t)(n0 + i) * CC + c0 + threadIdx.x;
        hp[idx] = h;
        lp[idx] = l;
    }
}

__global__ void __launch_bounds__(256)
combine_qk(const float* __restrict__ Wq, const float* __restrict__ Wk,
           const float* __restrict__ bq, const float* __restrict__ bk,
           __nv_bfloat16* __restrict__ wh, __nv_bfloat16* __restrict__ wl,
           float* __restrict__ bqk, float* __restrict__ rowsum) {
    int i = blockIdx.x * 256 + threadIdx.x;
    if (i < 2 * C8 * CC) {
        int row = i / CC, col = i % CC;
        float v = (row < C8) ? Wq[row * CC + col] : Wk[(row - C8) * CC + col];
        __nv_bfloat16 h, l;
        split_bf16(v, h, l);
        wh[i] = h;
        wl[i] = l;
        if (i < 2 * C8) bqk[i] = (i < C8) ? bq[i] : bk[i - C8];
    }
    if (i < BB * NN_) rowsum[i] = 0.f;
}

__global__ void __launch_bounds__(256)
cvt_bf16(const float* __restrict__ s, __nv_bfloat16* __restrict__ h, int n) {
    int i = blockIdx.x * 256 + threadIdx.x;
    if (i < n) h[i] = __float2bfloat16(s[i]);
}

// ---------------------------------------------------------------------------
extern "C" void kernel_launch(void* const* d_in, const int* in_sizes, int n_in,
                              void* d_out, int out_size) {
    const float* x = (const float*)d_in[0];
    const float* Wq = (const float*)d_in[1];
    const float* bq = (const float*)d_in[2];
    const float* Wk = (const float*)d_in[3];
    const float* bk = (const float*)d_in[4];
    const float* Wv = (const float*)d_in[5];
    const float* bv = (const float*)d_in[6];
    const float* gamma = (const float*)d_in[7];
    float* out = (float*)d_out;

    __nv_bfloat16 *xth, *xtl, *wqkh, *wqkl, *wvh, *qkth, *qktl, *vh, *sh;
    float *bqk, *rowsum;
    cudaGetSymbolAddress((void**)&xth, g_xth);
    cudaGetSymbolAddress((void**)&xtl, g_xtl);
    cudaGetSymbolAddress((void**)&wqkh, g_wqkh);
    cudaGetSymbolAddress((void**)&wqkl, g_wqkl);
    cudaGetSymbolAddress((void**)&bqk, g_bqk);
    cudaGetSymbolAddress((void**)&wvh, g_wvh);
    cudaGetSymbolAddress((void**)&qkth, g_qkth);
    cudaGetSymbolAddress((void**)&qktl, g_qktl);
    cudaGetSymbolAddress((void**)&vh, g_vh);
    cudaGetSymbolAddress((void**)&sh, g_sh);
    cudaGetSymbolAddress((void**)&rowsum, g_rowsum);

    // Side streams + events (host resources; created once, reused).
    static cudaStream_t s1 = nullptr, s2 = nullptr;
    static cudaEvent_t e0, e1, ex, ev;
    static cudaEvent_t eatt[BB];
    if (!s1) {
        cudaStreamCreateWithFlags(&s1, cudaStreamNonBlocking);
        cudaStreamCreateWithFlags(&s2, cudaStreamNonBlocking);
        cudaEventCreateWithFlags(&e0, cudaEventDisableTiming);
        cudaEventCreateWithFlags(&e1, cudaEventDisableTiming);
        cudaEventCreateWithFlags(&ex, cudaEventDisableTiming);
        cudaEventCreateWithFlags(&ev, cudaEventDisableTiming);
        for (int b = 0; b < BB; b++)
            cudaEventCreateWithFlags(&eatt[b], cudaEventDisableTiming);
    }

    // smem = STAGES * (AH*BM + BH*BN) * 40 elems * 2 B
    constexpr int SM_QK = 3 * (2 * 128 + 2 * 64) * 40 * 2;    // 92160 (T=3,S=3,BN=64)
    constexpr int SM_ATT = 3 * (2 * 128 + 1 * 128) * 40 * 2;  // 92160 (T=2,S=3)
    constexpr int SM_V = 4 * (128 + 128) * 40 * 2;            // 81920 (T=1,S=4)
    constexpr int SM_OUT = 3 * (64 + 128) * 40 * 2;           // 46080 (T=1,S=3,BM=64)
    cudaFuncSetAttribute(
        mma_gemm<128, 64, 3, 3, true, 1, true, false, false, false>,
        cudaFuncAttributeMaxDynamicSharedMemorySize, SM_QK);
    cudaFuncSetAttribute(
        mma_gemm<128, 128, 1, 4, false, 2, true, false, false, false>,
        cudaFuncAttributeMaxDynamicSharedMemorySize, SM_V);
    cudaFuncSetAttribute(
        mma_gemm<128, 128, 2, 3, false, 3, false, false, false, false>,
        cudaFuncAttributeMaxDynamicSharedMemorySize, SM_ATT);
    cudaFuncSetAttribute(
        mma_gemm<64, 128, 1, 3, false, 0, false, true, true, true>,
        cudaFuncAttributeMaxDynamicSharedMemorySize, SM_OUT);

    const size_t sX = (size_t)CC * NN_;
    const size_t sXT = (size_t)NN_ * CC;
    const size_t sQK = (size_t)NN_ * 2 * C8;
    const size_t sAtt = (size_t)NN_ * NN_;

    // ---- fork: stream0 (xT + qk + att chain), s1 (weights), s2 (v, out) ----
    cudaEventRecord(e0, 0);
    cudaStreamWaitEvent(s1, e0, 0);
    cudaStreamWaitEvent(s2, e0, 0);

    // s1: [Wq;Wk] split + bias + rowsum zero
    combine_qk<<<(2 * C8 * CC + 255) / 256, 256, 0, s1>>>(
        Wq, Wk, bq, bk, wqkh, wqkl, bqk, rowsum);
    cudaEventRecord(e1, s1);

    // s2: Wv convert
    cvt_bf16<<<(CC * CC + 255) / 256, 256, 0, s2>>>(Wv, wvh, CC * CC);

    // stream0: x transpose+split
    transpose_split_x<<<dim3(NN_ / 32, CC / 32, BB), dim3(32, 8)>>>(x, xth, xtl);
    cudaEventRecord(ex, 0);

    // s2: v[b,c,n] = Wv @ x[b] + bv (all batches; runs under qk+att)
    cudaStreamWaitEvent(s2, ex, 0);
    mma_gemm<128, 128, 1, 4, false, 2, true, false, false, false>
        <<<dim3(NN_ / 128, CC / 128, BB), 256, SM_V, s2>>>(
            wvh, nullptr, xth, nullptr, CC, CC, CC, 0, sXT, bv,
            nullptr, vh, nullptr, NN_, sX, nullptr, nullptr, nullptr, 0);
    cudaEventRecord(ev, s2);

    // stream0: qk^T for all batches (BN=64 -> 256 CTAs)
    cudaStreamWaitEvent(0, e1, 0);
    mma_gemm<128, 64, 3, 3, true, 1, true, false, false, false>
        <<<dim3(NN_ / 64, 1, BB), 256, SM_QK>>>(
            wqkh, wqkl, xth, xtl, CC, CC, CC, 0, sXT, bqk,
            nullptr, qkth, qktl, 2 * C8, sQK, nullptr, nullptr, nullptr, 0);

    // Per-batch pipeline: att(b) on stream0, out(b) on s2 (waits att(b) + v).
    cudaStreamWaitEvent(s2, ev, 0);  // out launches ordered after v on s2
    for (int b = 0; b < BB; b++) {
        mma_gemm<128, 128, 2, 3, false, 3, false, false, false, false>
            <<<dim3(NN_ / 128, NN_ / 128, 1), 256, SM_ATT>>>(
                qkth, qktl, qkth + C8, nullptr, C8, 2 * C8, 2 * C8, sQK, sQK,
                nullptr, nullptr, sh, nullptr, NN_, sAtt, nullptr, nullptr,
                rowsum, b);
        cudaEventRecord(eatt[b], 0);

        cudaStreamWaitEvent(s2, eatt[b], 0);
        mma_gemm<64, 128, 1, 3, false, 0, false, true, true, true>
            <<<dim3(CC / 64, NN_ / 128, 1), 256, SM_OUT, s2>>>(
                vh, nullptr, sh, nullptr, NN_, NN_, NN_, sX, sAtt, nullptr,
                out, nullptr, nullptr, NN_, sX, x, gamma, rowsum, b);
    }
    // join s2 back into stream0 (last out must complete before return).
    cudaEventRecord(ev, s2);
    cudaStreamWaitEvent(0, ev, 0);
}

// round 15
// speedup vs baseline: 1.0867x; 1.0867x over previous
#include <cuda_runtime.h>
#include <cuda_bf16.h>
#include <cstdint>
#include <cstddef>

#define BB 4
#define CC 512
#define NN_ 4096
#define C8 64

// ---------------- scratch (__device__ globals; allocation-free rule) -------
__device__ __align__(128) __nv_bfloat16 g_xth[(size_t)BB * NN_ * CC];  // x^T hi [b,n,c]
__device__ __align__(128) __nv_bfloat16 g_xtl[(size_t)BB * NN_ * CC];  // x^T lo
__device__ __align__(128) __nv_bfloat16 g_wqkh[2 * C8 * CC];           // [Wq;Wk] hi
__device__ __align__(128) __nv_bfloat16 g_wqkl[2 * C8 * CC];           // [Wq;Wk] lo
__device__ __align__(128) float g_bqk[2 * C8];                          // [bq;bk]
__device__ __align__(128) __nv_bfloat16 g_wvh[CC * CC];                // Wv hi
__device__ __align__(128) __nv_bfloat16 g_qkth[(size_t)BB * NN_ * 2 * C8]; // qk^T hi
__device__ __align__(128) __nv_bfloat16 g_qktl[(size_t)BB * NN_ * 2 * C8]; // qk^T lo
__device__ __align__(128) __nv_bfloat16 g_vh[(size_t)BB * CC * NN_];   // v hi [b,c,n]
__device__ __align__(128) __nv_bfloat16 g_sh[(size_t)BB * NN_ * NN_];  // e=exp(att)
__device__ __align__(128) float g_rowsum[(size_t)BB * NN_];            // sum_j e [b,i]

// ---------------- helpers ---------------------------------------------------
__device__ __forceinline__ uint32_t smem_u32(const void* p) {
    uint32_t a;
    asm("{ .reg .u64 t; cvta.to.shared.u64 t, %1; cvt.u32.u64 %0, t; }"
        : "=r"(a) : "l"(p));
    return a;
}
__device__ __forceinline__ void cp16(uint32_t dst, const void* src) {
    asm volatile("cp.async.cg.shared.global [%0], [%1], 16;" :: "r"(dst), "l"(src));
}
template <int N>
__device__ __forceinline__ void wait_group() {
    asm volatile("cp.async.wait_group %0;" :: "n"(N) : "memory");
}
__device__ __forceinline__ void ldsm4(uint32_t* r, uint32_t addr) {
    asm volatile("ldmatrix.sync.aligned.m8n8.x4.shared.b16 {%0,%1,%2,%3}, [%4];"
                 : "=r"(r[0]), "=r"(r[1]), "=r"(r[2]), "=r"(r[3]) : "r"(addr));
}
__device__ __forceinline__ void mma16816(float* d, const uint32_t* a, const uint32_t* b) {
    asm volatile(
        "mma.sync.aligned.m16n8k16.row.col.f32.bf16.bf16.f32 "
        "{%0,%1,%2,%3}, {%4,%5,%6,%7}, {%8,%9}, {%0,%1,%2,%3};"
        : "+f"(d[0]), "+f"(d[1]), "+f"(d[2]), "+f"(d[3])
        : "r"(a[0]), "r"(a[1]), "r"(a[2]), "r"(a[3]), "r"(b[0]), "r"(b[1]));
}
__device__ __forceinline__ void split_bf16(float v, __nv_bfloat16& h, __nv_bfloat16& l) {
    h = __float2bfloat16(v);
    l = __float2bfloat16(v - __bfloat162float(h));
}

// ---------------------------------------------------------------------------
// bf16 HMMA GEMM, multistage cp.async pipeline (single barrier / iteration).
//   C[b,m,n] = sum_k A(m,k)*B(n,k)
// TERMS: 3 = (Ah+Al)x(Bh+Bl); 2 = (Ah+Al)xBh; 1 = AhxBh.
// OUTMODE: 0 = fp32 (opt. gamma*acc*invrowsum + resid), 1 = split bf16 hi+lo,
//          2 = bf16 hi only, 3 = bf16 exp(acc) + row-sum atomics.
// RS: in mode 0, scale acc by 1/rowsum[b,n]. TRANS_OUT: output [n][m].
// XM: blockIdx.x = m. Block: 256 thr = 8 warps (2x4). BK = 32. STAGES >= 3.
// ---------------------------------------------------------------------------
template <int BM, int BN, int TERMS, int STAGES, bool TRANS_OUT, int OUTMODE,
          bool HAS_BIAS, bool HAS_RESID, bool XM, bool RS>
__global__ void __launch_bounds__(256)
mma_gemm(const __nv_bfloat16* __restrict__ Ah, const __nv_bfloat16* __restrict__ Al,
         const __nv_bfloat16* __restrict__ Bh, const __nv_bfloat16* __restrict__ Bl,
         int K, int lda, int ldb, size_t sA, size_t sB,
         const float* __restrict__ bias,
         float* __restrict__ Cf,
         __nv_bfloat16* __restrict__ Oh, __nv_bfloat16* __restrict__ Ol,
         int ldc, size_t sC,
         const float* __restrict__ resid, const float* __restrict__ gamma,
         float* __restrict__ rowsum) {
    constexpr int AH = (TERMS >= 2) ? 2 : 1;   // A halves staged
    constexpr int BH = (TERMS >= 3) ? 2 : 1;   // B halves staged
    constexpr int LDSS = 40;                   // padded k-stride (bf16)
    constexpr int A_HALF = BM * LDSS;
    constexpr int B_HALF = BN * LDSS;
    constexpr int BOFF = STAGES * AH * A_HALF; // B area start (elems)
    extern __shared__ __nv_bfloat16 sm[];

    const int tid = threadIdx.x;
    const int lane = tid & 31, warp = tid >> 5;
    const int wm = warp >> 2, wn = warp & 3;
    constexpr int WTM = BM / 2, WTN = BN / 4;
    constexpr int MT = WTM / 16, NT = WTN / 8;

    const int bm0 = (XM ? blockIdx.x : blockIdx.y) * BM;
    const int bn0 = (XM ? blockIdx.y : blockIdx.x) * BN;
    const int b = blockIdx.z;
    const __nv_bfloat16* aptr[2] = {Ah + (size_t)b * sA,
                                    (AH > 1) ? Al + (size_t)b * sA : Ah};
    const __nv_bfloat16* bptr[2] = {Bh + (size_t)b * sB,
                                    (BH > 1) ? Bl + (size_t)b * sB : Bh};
    const uint32_t smb = smem_u32(sm);

    const int mat = lane >> 3, r8 = lane & 7;
    const uint32_t lmoff = 2 * (((mat & 1) * 8 + r8) * LDSS + (mat >> 1) * 8);

    float acc[MT][NT][4];
#pragma unroll
    for (int i = 0; i < MT; i++)
#pragma unroll
        for (int j = 0; j < NT; j++)
#pragma unroll
            for (int e = 0; e < 4; e++) acc[i][j][e] = 0.f;

    auto load_stage = [&](int stage, int kt) {
        constexpr int CA = BM * 4 * AH / 256;
#pragma unroll
        for (int i = 0; i < CA; i++) {
            int idx = tid + i * 256;
            int half = idx / (BM * 4);
            int rem = idx - half * BM * 4;
            int r = rem >> 2, seg = rem & 3;
            const __nv_bfloat16* src =
                aptr[half] + (size_t)(bm0 + r) * lda + kt * 32 + seg * 8;
            uint32_t dst = smb + ((stage * AH + half) * A_HALF + r * LDSS + seg * 8) * 2;
            cp16(dst, src);
        }
        constexpr int CB = BN * 4 * BH / 256;
#pragma unroll
        for (int i = 0; i < CB; i++) {
            int idx = tid + i * 256;
            int half = idx / (BN * 4);
            int rem = idx - half * BN * 4;
            int r = rem >> 2, seg = rem & 3;
            const __nv_bfloat16* src =
                bptr[half] + (size_t)(bn0 + r) * ldb + kt * 32 + seg * 8;
            uint32_t dst = smb +
                (BOFF + (stage * BH + half) * B_HALF + r * LDSS + seg * 8) * 2;
            cp16(dst, src);
        }
        asm volatile("cp.async.commit_group;" ::: "memory");
    };

    const int KT = K / 32;
#pragma unroll
    for (int i = 0; i < STAGES - 1; i++)
        if (i < KT) load_stage(i, i);

    for (int kt = 0; kt < KT; kt++) {
        const int rem = KT - 1 - kt;
        if (rem >= STAGES - 2) wait_group<STAGES - 2>();
        else if (STAGES >= 4 && rem == 2) wait_group<2>();
        else if (rem == 1) wait_group<1>();
        else wait_group<0>();
        __syncthreads();
        if (kt + STAGES - 1 < KT)
            load_stage((kt + STAGES - 1) % STAGES, kt + STAGES - 1);

        const int s = kt % STAGES;
        const uint32_t aHi = smb + 2 * ((s * AH) * A_HALF);
        const uint32_t bHi = smb + 2 * (BOFF + (s * BH) * B_HALF);
#pragma unroll
        for (int ks = 0; ks < 2; ks++) {
            const int kk = ks * 16;
            uint32_t bh[NT][2], bl[NT][2];
#pragma unroll
            for (int p = 0; p < NT / 2; p++) {
                uint32_t t[4];
                uint32_t ab = bHi + 2 * ((wn * WTN + p * 16) * LDSS + kk) + lmoff;
                ldsm4(t, ab);
                bh[2 * p][0] = t[0]; bh[2 * p + 1][0] = t[1];
                bh[2 * p][1] = t[2]; bh[2 * p + 1][1] = t[3];
                if constexpr (BH > 1) {
                    ldsm4(t, ab + 2 * B_HALF);
                    bl[2 * p][0] = t[0]; bl[2 * p + 1][0] = t[1];
                    bl[2 * p][1] = t[2]; bl[2 * p + 1][1] = t[3];
                }
            }
#pragma unroll
            for (int mt = 0; mt < MT; mt++) {
                uint32_t ah[4], al[4];
                uint32_t aa = aHi + 2 * ((wm * WTM + mt * 16) * LDSS + kk) + lmoff;
                ldsm4(ah, aa);
                if constexpr (AH > 1) ldsm4(al, aa + 2 * A_HALF);
#pragma unroll
                for (int nt = 0; nt < NT; nt++) {
                    mma16816(acc[mt][nt], ah, bh[nt]);
                    if constexpr (BH > 1) mma16816(acc[mt][nt], ah, bl[nt]);
                    if constexpr (AH > 1) mma16816(acc[mt][nt], al, bh[nt]);
                }
            }
        }
    }
    __syncthreads();

    float g = 1.f;
    if constexpr (HAS_RESID) g = __ldg(gamma);

#pragma unroll
    for (int mt = 0; mt < MT; mt++) {
        const int r = bm0 + wm * WTM + mt * 16 + (lane >> 2);
        float bi0 = 0.f, bi1 = 0.f;
        if constexpr (HAS_BIAS) { bi0 = bias[r]; bi1 = bias[r + 8]; }
        float sum_r = 0.f, sum_r8 = 0.f;
#pragma unroll
        for (int nt = 0; nt < NT; nt++) {
            const int c = bn0 + wn * WTN + nt * 8 + (lane & 3) * 2;
            float v[4] = {acc[mt][nt][0] + bi0, acc[mt][nt][1] + bi0,
                          acc[mt][nt][2] + bi1, acc[mt][nt][3] + bi1};
            if constexpr (OUTMODE == 3) {
                __nv_bfloat16 e[4];
#pragma unroll
                for (int q = 0; q < 4; q++) e[q] = __float2bfloat16(__expf(v[q]));
                sum_r  += __bfloat162float(e[0]) + __bfloat162float(e[1]);
                sum_r8 += __bfloat162float(e[2]) + __bfloat162float(e[3]);
                size_t i0 = (size_t)b * sC + (size_t)r * ldc + c;
                size_t i1 = (size_t)b * sC + (size_t)(r + 8) * ldc + c;
                *reinterpret_cast<__nv_bfloat162*>(&Oh[i0]) = __nv_bfloat162(e[0], e[1]);
                *reinterpret_cast<__nv_bfloat162*>(&Oh[i1]) = __nv_bfloat162(e[2], e[3]);
            } else if constexpr (!TRANS_OUT) {
#pragma unroll
                for (int p = 0; p < 2; p++) {
                    const int row = r + p * 8;
                    size_t idx = (size_t)b * sC + (size_t)row * ldc + c;
                    if constexpr (OUTMODE == 1) {
                        __nv_bfloat16 h0, l0, h1, l1;
                        split_bf16(v[p * 2 + 0], h0, l0);
                        split_bf16(v[p * 2 + 1], h1, l1);
                        *reinterpret_cast<__nv_bfloat162*>(&Oh[idx]) =
                            __nv_bfloat162(h0, h1);
                        *reinterpret_cast<__nv_bfloat162*>(&Ol[idx]) =
                            __nv_bfloat162(l0, l1);
                    } else if constexpr (OUTMODE == 2) {
                        *reinterpret_cast<__nv_bfloat162*>(&Oh[idx]) =
                            __nv_bfloat162(__float2bfloat16(v[p * 2 + 0]),
                                           __float2bfloat16(v[p * 2 + 1]));
                    } else {
                        float s0 = 1.f, s1 = 1.f;
                        if constexpr (RS) {
                            float2 rsv = *reinterpret_cast<const float2*>(
                                &rowsum[(size_t)b * NN_ + c]);
                            s0 = 1.0f / rsv.x;
                            s1 = 1.0f / rsv.y;
                        }
                        float2 o;
                        if constexpr (HAS_RESID) {
                            float2 rx = *reinterpret_cast<const float2*>(&resid[idx]);
                            o.x = g * v[p * 2 + 0] * s0 + rx.x;
                            o.y = g * v[p * 2 + 1] * s1 + rx.y;
                        } else {
                            o.x = v[p * 2 + 0] * s0;
                            o.y = v[p * 2 + 1] * s1;
                        }
                        *reinterpret_cast<float2*>(&Cf[idx]) = o;
                    }
                }
            } else {
                const int rr[4] = {r, r, r + 8, r + 8};
                const int ccx[4] = {c, c + 1, c, c + 1};
#pragma unroll
                for (int e = 0; e < 4; e++) {
                    size_t idx = (size_t)b * sC + (size_t)ccx[e] * ldc + rr[e];
                    if constexpr (OUTMODE == 1) {
                        __nv_bfloat16 h, l;
                        split_bf16(v[e], h, l);
                        Oh[idx] = h;
                        Ol[idx] = l;
                    } else if constexpr (OUTMODE == 2) {
                        Oh[idx] = __float2bfloat16(v[e]);
                    } else {
                        Cf[idx] = v[e];
                    }
                }
            }
        }
        if constexpr (OUTMODE == 3) {
            sum_r  += __shfl_xor_sync(0xffffffffu, sum_r, 1);
            sum_r  += __shfl_xor_sync(0xffffffffu, sum_r, 2);
            sum_r8 += __shfl_xor_sync(0xffffffffu, sum_r8, 1);
            sum_r8 += __shfl_xor_sync(0xffffffffu, sum_r8, 2);
            if ((lane & 3) == 0) {
                atomicAdd(&rowsum[(size_t)b * NN_ + r], sum_r);
                atomicAdd(&rowsum[(size_t)b * NN_ + r + 8], sum_r8);
            }
        }
    }
}

// ---------------------------------------------------------------------------
__global__ void __launch_bounds__(256)
transpose_split_x(const float* __restrict__ x,
                  __nv_bfloat16* __restrict__ th, __nv_bfloat16* __restrict__ tl) {
    __shared__ float t[32][33];
    const int b = blockIdx.z;
    const int c0 = blockIdx.y * 32, n0 = blockIdx.x * 32;
    const float* xp = x + (size_t)b * CC * NN_;
#pragma unroll
    for (int i = threadIdx.y; i < 32; i += 8)
        t[i][threadIdx.x] = xp[(size_t)(c0 + i) * NN_ + n0 + threadIdx.x];
    __syncthreads();
    __nv_bfloat16* hp = th + (size_t)b * NN_ * CC;
    __nv_bfloat16* lp = tl + (size_t)b * NN_ * CC;
#pragma unroll
    for (int i = threadIdx.y; i < 32; i += 8) {
        float v = t[threadIdx.x][i];
        __nv_bfloat16 h, l;
        split_bf16(v, h, l);
        size_t idx = (size_t)(n0 + i) * CC + c0 + threadIdx.x;
        hp[idx] = h;
        lp[idx] = l;
    }
}

__global__ void __launch_bounds__(256)
combine_qk(const float* __restrict__ Wq, const float* __restrict__ Wk,
           const float* __restrict__ bq, const float* __restrict__ bk,
           __nv_bfloat16* __restrict__ wh, __nv_bfloat16* __restrict__ wl,
           float* __restrict__ bqk, float* __restrict__ rowsum) {
    int i = blockIdx.x * 256 + threadIdx.x;
    if (i < 2 * C8 * CC) {
        int row = i / CC, col = i % CC;
        float v = (row < C8) ? Wq[row * CC + col] : Wk[(row - C8) * CC + col];
        __nv_bfloat16 h, l;
        split_bf16(v, h, l);
        wh[i] = h;
        wl[i] = l;
        if (i < 2 * C8) bqk[i] = (i < C8) ? bq[i] : bk[i - C8];
    }
    if (i < BB * NN_) rowsum[i] = 0.f;
}

__global__ void __launch_bounds__(256)
cvt_bf16(const float* __restrict__ s, __nv_bfloat16* __restrict__ h, int n) {
    int i = blockIdx.x * 256 + threadIdx.x;
    if (i < n) h[i] = __float2bfloat16(s[i]);
}

// ---------------------------------------------------------------------------
extern "C" void kernel_launch(void* const* d_in, const int* in_sizes, int n_in,
                              void* d_out, int out_size) {
    const float* x = (const float*)d_in[0];
    const float* Wq = (const float*)d_in[1];
    const float* bq = (const float*)d_in[2];
    const float* Wk = (const float*)d_in[3];
    const float* bk = (const float*)d_in[4];
    const float* Wv = (const float*)d_in[5];
    const float* bv = (const float*)d_in[6];
    const float* gamma = (const float*)d_in[7];
    float* out = (float*)d_out;

    __nv_bfloat16 *xth, *xtl, *wqkh, *wqkl, *wvh, *qkth, *qktl, *vh, *sh;
    float *bqk, *rowsum;
    cudaGetSymbolAddress((void**)&xth, g_xth);
    cudaGetSymbolAddress((void**)&xtl, g_xtl);
    cudaGetSymbolAddress((void**)&wqkh, g_wqkh);
    cudaGetSymbolAddress((void**)&wqkl, g_wqkl);
    cudaGetSymbolAddress((void**)&bqk, g_bqk);
    cudaGetSymbolAddress((void**)&wvh, g_wvh);
    cudaGetSymbolAddress((void**)&qkth, g_qkth);
    cudaGetSymbolAddress((void**)&qktl, g_qktl);
    cudaGetSymbolAddress((void**)&vh, g_vh);
    cudaGetSymbolAddress((void**)&sh, g_sh);
    cudaGetSymbolAddress((void**)&rowsum, g_rowsum);

    // Side streams + events (host resources; created once, reused).
    static cudaStream_t s1 = nullptr, s2 = nullptr;
    static cudaEvent_t e0, e1, ex, ev;
    if (!s1) {
        cudaStreamCreateWithFlags(&s1, cudaStreamNonBlocking);
        cudaStreamCreateWithFlags(&s2, cudaStreamNonBlocking);
        cudaEventCreateWithFlags(&e0, cudaEventDisableTiming);
        cudaEventCreateWithFlags(&e1, cudaEventDisableTiming);
        cudaEventCreateWithFlags(&ex, cudaEventDisableTiming);
        cudaEventCreateWithFlags(&ev, cudaEventDisableTiming);
    }

    // smem = STAGES * (AH*BM + BH*BN) * 40 elems * 2 B
    constexpr int SM_QK = 3 * (2 * 128 + 2 * 64) * 40 * 2;    // 92160 (T=3,S=3,BN=64)
    constexpr int SM_ATT = 3 * (2 * 128 + 1 * 128) * 40 * 2;  // 92160 (T=2,S=3)
    constexpr int SM_1 = 3 * (128 + 128) * 40 * 2;            // 61440 (T=1,S=3) -> 3 CTAs/SM
    cudaFuncSetAttribute(
        mma_gemm<128, 64, 3, 3, true, 1, true, false, false, false>,
        cudaFuncAttributeMaxDynamicSharedMemorySize, SM_QK);
    cudaFuncSetAttribute(
        mma_gemm<128, 128, 1, 3, false, 2, true, false, false, false>,
        cudaFuncAttributeMaxDynamicSharedMemorySize, SM_1);
    cudaFuncSetAttribute(
        mma_gemm<128, 128, 2, 3, false, 3, false, false, false, false>,
        cudaFuncAttributeMaxDynamicSharedMemorySize, SM_ATT);
    cudaFuncSetAttribute(
        mma_gemm<128, 128, 1, 3, false, 0, false, true, true, true>,
        cudaFuncAttributeMaxDynamicSharedMemorySize, SM_1);

    const size_t sX = (size_t)CC * NN_;
    const size_t sXT = (size_t)NN_ * CC;
    const size_t sQK = (size_t)NN_ * 2 * C8;
    const size_t sAtt = (size_t)NN_ * NN_;

    // ---- fork: stream0 (xT + qk + att + out), s1 (weights), s2 (v chain) ----
    cudaEventRecord(e0, 0);
    cudaStreamWaitEvent(s1, e0, 0);
    cudaStreamWaitEvent(s2, e0, 0);

    // s1: [Wq;Wk] split + bias + rowsum zero
    combine_qk<<<(2 * C8 * CC + 255) / 256, 256, 0, s1>>>(
        Wq, Wk, bq, bk, wqkh, wqkl, bqk, rowsum);
    cudaEventRecord(e1, s1);

    // s2: Wv convert (v-proj waits for xT below)
    cvt_bf16<<<(CC * CC + 255) / 256, 256, 0, s2>>>(Wv, wvh, CC * CC);

    // stream0: x transpose+split
    transpose_split_x<<<dim3(NN_ / 32, CC / 32, BB), dim3(32, 8)>>>(x, xth, xtl);
    cudaEventRecord(ex, 0);

    // s2: v[b,c,n] = Wv @ x[b] + bv (single-term bf16) — runs under qk+att
    cudaStreamWaitEvent(s2, ex, 0);
    mma_gemm<128, 128, 1, 3, false, 2, true, false, false, false>
        <<<dim3(NN_ / 128, CC / 128, BB), 256, SM_1, s2>>>(
            wvh, nullptr, xth, nullptr, CC, CC, CC, 0, sXT, bv,
            nullptr, vh, nullptr, NN_, sX, nullptr, nullptr, nullptr);
    cudaEventRecord(ev, s2);

    // stream0: qk^T (M=128, BN=64 -> 256 CTAs), then att
    cudaStreamWaitEvent(0, e1, 0);
    mma_gemm<128, 64, 3, 3, true, 1, true, false, false, false>
        <<<dim3(NN_ / 64, 1, BB), 256, SM_QK>>>(
            wqkh, wqkl, xth, xtl, CC, CC, CC, 0, sXT, bqk,
            nullptr, qkth, qktl, 2 * C8, sQK, nullptr, nullptr, nullptr);

    mma_gemm<128, 128, 2, 3, false, 3, false, false, false, false>
        <<<dim3(NN_ / 128, NN_ / 128, BB), 256, SM_ATT>>>(
            qkth, qktl, qkth + C8, nullptr, C8, 2 * C8, 2 * C8, sQK, sQK,
            nullptr, nullptr, sh, nullptr, NN_, sAtt, nullptr, nullptr, rowsum);

    // join v, then out
    cudaStreamWaitEvent(0, ev, 0);
    mma_gemm<128, 128, 1, 3, false, 0, false, true, true, true>
        <<<dim3(CC / 128, NN_ / 128, BB), 256, SM_1>>>(
            vh, nullptr, sh, nullptr, NN_, NN_, NN_, sX, sAtt, nullptr,
            out, nullptr, nullptr, NN_, sX, x, gamma, rowsum);
}